// round 1
// baseline (speedup 1.0000x reference)
#include <cuda_runtime.h>
#include <stdint.h>

// SpikeFP64Divider: reference is a gate-level FP64 restoring divider operating on
// rows of 64 floats in {0,1}. We replicate the EXACT circuit semantics in integer
// logic (including its quirks: 13-bit modular exponent math, subnormals treated as
// normals with implicit leading 1, and the mantissa-round carry-out that is
// structurally always 0 so rounding 1.11..1 up does NOT bump the exponent).
//
// Bit packing convention: column c of a row maps to bit (63-c) of a uint64, i.e.
// the packed word reads like a real IEEE-754 double (sign @63, exp @62..52,
// mantissa @51..0).

static __device__ __forceinline__ uint32_t f2b(float f) { return f > 0.5f ? 1u : 0u; }

__global__ __launch_bounds__(256, 1) void spike_div_kernel(
    const float* __restrict__ A, const float* __restrict__ B, float* __restrict__ O)
{
    __shared__ uint32_t pa[256][2];
    __shared__ uint32_t pb[256][2];
    __shared__ uint32_t po[256][2];

    const int tid = threadIdx.x;
    const long long base = (long long)blockIdx.x * (256LL * 64LL);

    pa[tid][0] = 0u; pa[tid][1] = 0u;
    pb[tid][0] = 0u; pb[tid][1] = 0u;
    __syncthreads();

    // ---- Phase 1: coalesced load + bit-pack via shared atomicOr ----
    const float4* A4 = reinterpret_cast<const float4*>(A + base);
    const float4* B4 = reinterpret_cast<const float4*>(B + base);
#pragma unroll
    for (int j = 0; j < 16; j++) {
        const int i = tid + j * 256;      // float4 index within tile (0..4095)
        const int r = i >> 4;             // row within tile (16 float4 per row)
        const int c = (i & 15) << 2;      // first column of this float4
        const int w = (c < 32) ? 1 : 0;   // word: cols 0..31 -> high word
        const int sh = 28 - (c & 31);     // nibble shift within word

        float4 va = A4[i];
        uint32_t na = (f2b(va.x) << 3) | (f2b(va.y) << 2) | (f2b(va.z) << 1) | f2b(va.w);
        atomicOr(&pa[r][w], na << sh);

        float4 vb = B4[i];
        uint32_t nb = (f2b(vb.x) << 3) | (f2b(vb.y) << 2) | (f2b(vb.z) << 1) | f2b(vb.w);
        atomicOr(&pb[r][w], nb << sh);
    }
    __syncthreads();

    // ---- Phase 2: one thread = one row, integer replica of the circuit ----
    {
        const uint64_t wa = ((uint64_t)pa[tid][1] << 32) | (uint64_t)pa[tid][0];
        const uint64_t wb = ((uint64_t)pb[tid][1] << 32) | (uint64_t)pb[tid][0];

        const uint64_t M52 = 0x000FFFFFFFFFFFFFull;
        const uint32_t s_out = (uint32_t)((wa ^ wb) >> 63);
        const uint32_t ea = (uint32_t)(wa >> 52) & 0x7FFu;
        const uint32_t eb = (uint32_t)(wb >> 52) & 0x7FFu;
        const uint64_t ma = wa & M52;
        const uint64_t mb = wb & M52;

        const bool a_zero = (ea == 0u)     && (ma == 0ull);
        const bool b_zero = (eb == 0u)     && (mb == 0ull);
        const bool a_inf  = (ea == 0x7FFu) && (ma == 0ull);
        const bool b_inf  = (eb == 0x7FFu) && (mb == 0ull);
        const bool a_nan  = (ea == 0x7FFu) && (ma != 0ull);
        const bool b_nan  = (eb == 0x7FFu) && (mb != 0ull);

        const bool r_nan  = a_nan || b_nan || (a_zero && b_zero) || (a_inf && b_inf);
        const bool r_inf  = (!a_zero && b_zero) || (a_inf && !b_inf);
        const bool r_zero = (a_zero && !b_zero) || (!a_inf && b_inf);

        // 13-bit modular exponent arithmetic, exactly as the ripple circuits do.
        int exp13 = ((int)ea - (int)eb + 1023) & 8191;

        // Restoring division: 56 shift-steps + 1 final step -> 57-bit quotient.
        uint64_t Rr = (1ull << 53) | (ma << 1);
        const uint64_t Dd = (1ull << 53) | (mb << 1);
        uint64_t Q = 0ull;
#pragma unroll
        for (int i = 0; i < 56; i++) {
            const uint64_t t = Rr - Dd;
            const bool ge = (Rr >= Dd);
            Q = (Q << 1) | (uint64_t)ge;
            Rr = (ge ? t : Rr) << 1;   // invariant R < 2D < 2^55: never truncates
        }
        const bool geL = (Rr >= Dd);
        Q = (Q << 1) | (uint64_t)geL;
        const uint64_t Rfin = geL ? (Rr - Dd) : Rr;
        const bool remnz = (Rfin != 0ull);

        // Normalize + extract guard/round/sticky (Q bit 56 = first quotient bit).
        const uint32_t q0 = (uint32_t)(Q >> 56) & 1u;
        uint64_t mant;
        uint32_t rnd;
        bool sticky;
        if (q0) {
            mant   = (Q >> 4) & M52;
            rnd    = (uint32_t)(Q >> 3) & 1u;
            sticky = ((Q & 7ull) != 0ull) || remnz;
        } else {
            mant   = (Q >> 3) & M52;
            rnd    = (uint32_t)(Q >> 2) & 1u;
            sticky = ((Q & 3ull) != 0ull) || remnz;
            exp13  = (exp13 - 1) & 8191;
        }

        // Round-to-nearest-even. NOTE: the circuit's carry-out of the 53-bit
        // incrementer is structurally 0, so a mantissa overflow wraps to 0
        // WITHOUT incrementing the exponent. Replicate by masking only.
        const uint32_t lsb = (uint32_t)mant & 1u;
        const uint32_t rup = (rnd && (sticky || lsb)) ? 1u : 0u;
        mant = (mant + (uint64_t)rup) & M52;

        const uint32_t exp_field = (uint32_t)exp13 & 0x7FFu;
        const bool ovf = ((exp13 >> 11) & 3) != 0;
        const bool unf = (((exp13 >> 12) & 1) != 0) || (exp13 == 0);

        const uint64_t sbit = (uint64_t)s_out << 63;
        uint64_t out;
        if (r_nan)       out = sbit | (0x7FFull << 52) | (1ull << 51);
        else if (r_inf)  out = sbit | (0x7FFull << 52);
        else if (r_zero) out = sbit;
        else if (ovf)    out = sbit | (0x7FFull << 52);
        else if (unf)    out = sbit;
        else             out = sbit | ((uint64_t)exp_field << 52) | mant;

        po[tid][0] = (uint32_t)out;
        po[tid][1] = (uint32_t)(out >> 32);
    }
    __syncthreads();

    // ---- Phase 3: expand bits to floats, coalesced float4 stores ----
    float4* O4 = reinterpret_cast<float4*>(O + base);
#pragma unroll
    for (int j = 0; j < 16; j++) {
        const int i = tid + j * 256;
        const int r = i >> 4;
        const int c = (i & 15) << 2;
        const uint64_t w = ((uint64_t)po[r][1] << 32) | (uint64_t)po[r][0];
        float4 v;
        v.x = (float)((w >> (63 - c)) & 1ull);
        v.y = (float)((w >> (62 - c)) & 1ull);
        v.z = (float)((w >> (61 - c)) & 1ull);
        v.w = (float)((w >> (60 - c)) & 1ull);
        O4[i] = v;
    }
}

extern "C" void kernel_launch(void* const* d_in, const int* in_sizes, int n_in,
                              void* d_out, int out_size) {
    const float* A = (const float*)d_in[0];
    const float* B = (const float*)d_in[1];
    float* O = (float*)d_out;
    const int rows = in_sizes[0] / 64;       // 131072
    const int grid = rows / 256;             // 512 blocks, 256 rows each
    spike_div_kernel<<<grid, 256>>>(A, B, O);
}

// round 3
// speedup vs baseline: 1.8197x; 1.8197x over previous
#include <cuda_runtime.h>
#include <stdint.h>

// SpikeFP64Divider: gate-level FP64 restoring divider on rows of 64 {0,1} floats.
// Integer replica of the exact circuit semantics (13-bit modular exponent math,
// subnormal inputs treated as normals, mantissa-round carry-out structurally 0).
//
// R3 = R2 with the input-decode fix: flag bit of {0.0f,1.0f} is bit 29 of the
// IEEE encoding (0x3F800000), NOT bit 30.

static __device__ __forceinline__ uint32_t fbit(float f) {
    // inputs are exactly 0.0f or 1.0f: 1.0f = 0x3F800000, bit 29 is set
    return (__float_as_uint(f) >> 29) & 1u;
}

__global__ __launch_bounds__(256, 3) void spike_div_kernel(
    const float* __restrict__ A, const float* __restrict__ B, float* __restrict__ O)
{
    __shared__ uint32_t nibA[4096];   // 16 KB: one word per (row, 4-col group)
    __shared__ uint32_t nibB[4096];   // 16 KB
    __shared__ uint32_t po[256][2];   //  2 KB: packed results

    const int tid = threadIdx.x;
    const long long base = (long long)blockIdx.x * (256LL * 64LL);

    // ---- Phase 1: coalesced float4 loads -> nibble words (no atomics) ----
    const float4* A4 = reinterpret_cast<const float4*>(A + base);
    const float4* B4 = reinterpret_cast<const float4*>(B + base);
#pragma unroll
    for (int j = 0; j < 16; j++) {
        const int i = tid + j * 256;  // linear float4 index == nibble slot
        float4 va = A4[i];
        nibA[i] = (fbit(va.x) << 3) | (fbit(va.y) << 2) | (fbit(va.z) << 1) | fbit(va.w);
        float4 vb = B4[i];
        nibB[i] = (fbit(vb.x) << 3) | (fbit(vb.y) << 2) | (fbit(vb.z) << 1) | fbit(vb.w);
    }
    __syncthreads();

    // ---- Phase 2: one thread = one row ----
    {
        // Assemble 64-bit words. Rotated read order (step + tid/2) & 15 makes
        // every LDS step conflict-free: even lanes hit banks m, odd lanes 16+m.
        uint64_t wa = 0ull, wb = 0ull;
        const int rot = (tid >> 1) & 15;
        const int rowbase = tid << 4;
#pragma unroll
        for (int step = 0; step < 16; step++) {
            const int m = (step + rot) & 15;       // physical nibble index = col/4
            const int sh = 60 - 4 * m;             // col c -> bit (63-c)
            wa |= (uint64_t)nibA[rowbase | m] << sh;
            wb |= (uint64_t)nibB[rowbase | m] << sh;
        }

        const uint64_t M52 = 0x000FFFFFFFFFFFFFull;
        const uint32_t s_out = (uint32_t)((wa ^ wb) >> 63);
        const uint32_t ea = (uint32_t)(wa >> 52) & 0x7FFu;
        const uint32_t eb = (uint32_t)(wb >> 52) & 0x7FFu;
        const uint64_t ma = wa & M52;
        const uint64_t mb = wb & M52;

        const bool a_zero = (ea == 0u)     && (ma == 0ull);
        const bool b_zero = (eb == 0u)     && (mb == 0ull);
        const bool a_inf  = (ea == 0x7FFu) && (ma == 0ull);
        const bool b_inf  = (eb == 0x7FFu) && (mb == 0ull);
        const bool a_nan  = (ea == 0x7FFu) && (ma != 0ull);
        const bool b_nan  = (eb == 0x7FFu) && (mb != 0ull);

        const bool r_nan  = a_nan || b_nan || (a_zero && b_zero) || (a_inf && b_inf);
        const bool r_inf  = (!a_zero && b_zero) || (a_inf && !b_inf);
        const bool r_zero = (a_zero && !b_zero) || (!a_inf && b_inf);

        // 13-bit modular exponent arithmetic, as the ripple circuits do.
        int exp13 = ((int)ea - (int)eb + 1023) & 8191;

        // ---- Exact Q = floor(a * 2^56 / d), rem-nonzero flag ----
        // a, d are even 54-bit ints (exactly representable as doubles).
        const uint64_t a = (1ull << 53) | (ma << 1);
        const uint64_t d = (1ull << 53) | (mb << 1);
        const int64_t  ds = (int64_t)d;
        const double inv = 1.0 / (double)d;

        // digit 1: q1 = floor(a*2^28 / d); |true rem| < 2^55 so mod-2^64 signed ok
        int64_t q1 = (int64_t)((double)a * 0x1p28 * inv);
        int64_t r1 = (int64_t)((a << 28) - (uint64_t)q1 * d);
        if (r1 < 0)   { q1--; r1 += ds; }
        if (r1 < 0)   { q1--; r1 += ds; }
        if (r1 >= ds) { q1++; r1 -= ds; }

        // digit 2: q2 = floor(r1*2^28 / d)
        int64_t q2 = (int64_t)((double)r1 * 0x1p28 * inv);
        int64_t r2 = (int64_t)(((uint64_t)r1 << 28) - (uint64_t)q2 * d);
        if (r2 < 0)   { q2--; r2 += ds; }
        if (r2 < 0)   { q2--; r2 += ds; }
        if (r2 >= ds) { q2++; r2 -= ds; }

        const uint64_t Q = ((uint64_t)q1 << 28) + (uint64_t)q2;  // 57-bit quotient
        const bool remnz = (r2 != 0);

        // Normalize + guard/round/sticky (Q bit 56 = first quotient bit).
        const uint32_t q0 = (uint32_t)(Q >> 56) & 1u;
        uint64_t mant;
        uint32_t rnd;
        bool sticky;
        if (q0) {
            mant   = (Q >> 4) & M52;
            rnd    = (uint32_t)(Q >> 3) & 1u;
            sticky = ((Q & 7ull) != 0ull) || remnz;
        } else {
            mant   = (Q >> 3) & M52;
            rnd    = (uint32_t)(Q >> 2) & 1u;
            sticky = ((Q & 3ull) != 0ull) || remnz;
            exp13  = (exp13 - 1) & 8191;
        }

        // RNE; circuit's 53-bit incrementer carry-out is structurally 0:
        // mantissa overflow wraps to 0 WITHOUT exponent bump (mask only).
        const uint32_t lsb = (uint32_t)mant & 1u;
        const uint32_t rup = (rnd && (sticky || lsb)) ? 1u : 0u;
        mant = (mant + (uint64_t)rup) & M52;

        const uint32_t exp_field = (uint32_t)exp13 & 0x7FFu;
        const bool ovf = ((exp13 >> 11) & 3) != 0;
        const bool unf = (((exp13 >> 12) & 1) != 0) || (exp13 == 0);

        const uint64_t sbit = (uint64_t)s_out << 63;
        uint64_t out;
        if (r_nan)       out = sbit | (0x7FFull << 52) | (1ull << 51);
        else if (r_inf)  out = sbit | (0x7FFull << 52);
        else if (r_zero) out = sbit;
        else if (ovf)    out = sbit | (0x7FFull << 52);
        else if (unf)    out = sbit;
        else             out = sbit | ((uint64_t)exp_field << 52) | mant;

        po[tid][0] = (uint32_t)out;
        po[tid][1] = (uint32_t)(out >> 32);
    }
    __syncthreads();

    // ---- Phase 3: expand bits to floats, coalesced float4 stores ----
    float4* O4 = reinterpret_cast<float4*>(O + base);
#pragma unroll
    for (int j = 0; j < 16; j++) {
        const int i = tid + j * 256;
        const int r = i >> 4;
        const int c = (i & 15) << 2;
        const uint64_t w = ((uint64_t)po[r][1] << 32) | (uint64_t)po[r][0];  // broadcast LDS
        float4 v;
        v.x = (float)((uint32_t)(w >> (63 - c)) & 1u);
        v.y = (float)((uint32_t)(w >> (62 - c)) & 1u);
        v.z = (float)((uint32_t)(w >> (61 - c)) & 1u);
        v.w = (float)((uint32_t)(w >> (60 - c)) & 1u);
        O4[i] = v;
    }
}

extern "C" void kernel_launch(void* const* d_in, const int* in_sizes, int n_in,
                              void* d_out, int out_size) {
    const float* A = (const float*)d_in[0];
    const float* B = (const float*)d_in[1];
    float* O = (float*)d_out;
    const int rows = in_sizes[0] / 64;       // 131072
    const int grid = rows / 256;             // 512 blocks, 256 rows each
    spike_div_kernel<<<grid, 256>>>(A, B, O);
}

// round 4
// speedup vs baseline: 1.8658x; 1.0253x over previous
#include <cuda_runtime.h>
#include <stdint.h>

// SpikeFP64Divider: gate-level FP64 restoring divider on rows of 64 {0,1} floats.
// Integer replica of the exact circuit semantics (13-bit modular exponent math,
// subnormal inputs treated as normals, mantissa-round carry-out structurally 0).
//
// R4: barrier-free / smem-free. Bit transpose via warp ballot (pack) and warp
// shuffle (unpack). Each warp autonomously handles 32 rows. No __syncthreads,
// no shared memory, loads staged 16-deep for MLP.

__global__ __launch_bounds__(256) void spike_div_kernel(
    const float* __restrict__ A, const float* __restrict__ B, float* __restrict__ O)
{
    const unsigned FULL = 0xFFFFFFFFu;
    const int lane = threadIdx.x & 31;
    const int warp = threadIdx.x >> 5;

    // Each warp owns 32 consecutive rows = 2048 floats.
    const long long elemBase = (((long long)blockIdx.x * 8 + warp) * 32) * 64;
    const uint32_t* __restrict__ Au = reinterpret_cast<const uint32_t*>(A) + elemBase;
    const uint32_t* __restrict__ Bu = reinterpret_cast<const uint32_t*>(B) + elemBase;

    // ---- Pack: 64 half-rows per array; ballot k covers row k/2, half k&1 ----
    // Raw ballots captured by the owning lane (lane == k/2); brev applied after.
    uint32_t capA_hi = 0u, capA_lo = 0u, capB_hi = 0u, capB_lo = 0u;
#pragma unroll
    for (int k0 = 0; k0 < 64; k0 += 8) {
        uint32_t va[8], vb[8];
#pragma unroll
        for (int j = 0; j < 8; j++) va[j] = Au[(k0 + j) * 32 + lane];
#pragma unroll
        for (int j = 0; j < 8; j++) vb[j] = Bu[(k0 + j) * 32 + lane];
#pragma unroll
        for (int j = 0; j < 8; j++) {
            const int k = k0 + j;
            const uint32_t ba = __ballot_sync(FULL, va[j] != 0u);
            if (lane == (k >> 1)) { if (k & 1) capA_lo = ba; else capA_hi = ba; }
            const uint32_t bb = __ballot_sync(FULL, vb[j] != 0u);
            if (lane == (k >> 1)) { if (k & 1) capB_lo = bb; else capB_hi = bb; }
        }
    }
    // col c at bit 63-c: ballot bit l = col (half*32 + l) -> reverse each word.
    const uint64_t wa = ((uint64_t)__brev(capA_hi) << 32) | (uint64_t)__brev(capA_lo);
    const uint64_t wb = ((uint64_t)__brev(capB_hi) << 32) | (uint64_t)__brev(capB_lo);

    // ---- Circuit replica (one row per lane) ----
    const uint64_t M52 = 0x000FFFFFFFFFFFFFull;
    const uint32_t s_out = (uint32_t)((wa ^ wb) >> 63);
    const uint32_t ea = (uint32_t)(wa >> 52) & 0x7FFu;
    const uint32_t eb = (uint32_t)(wb >> 52) & 0x7FFu;
    const uint64_t ma = wa & M52;
    const uint64_t mb = wb & M52;

    const bool a_zero = (ea == 0u)     && (ma == 0ull);
    const bool b_zero = (eb == 0u)     && (mb == 0ull);
    const bool a_inf  = (ea == 0x7FFu) && (ma == 0ull);
    const bool b_inf  = (eb == 0x7FFu) && (mb == 0ull);
    const bool a_nan  = (ea == 0x7FFu) && (ma != 0ull);
    const bool b_nan  = (eb == 0x7FFu) && (mb != 0ull);

    const bool r_nan  = a_nan || b_nan || (a_zero && b_zero) || (a_inf && b_inf);
    const bool r_inf  = (!a_zero && b_zero) || (a_inf && !b_inf);
    const bool r_zero = (a_zero && !b_zero) || (!a_inf && b_inf);

    // 13-bit modular exponent arithmetic, as the ripple circuits do.
    int exp13 = ((int)ea - (int)eb + 1023) & 8191;

    // ---- Exact Q = floor(a * 2^56 / d) via 2 base-2^28 digits ----
    const uint64_t a = (1ull << 53) | (ma << 1);
    const uint64_t d = (1ull << 53) | (mb << 1);
    const int64_t  ds = (int64_t)d;
    const double inv = 1.0 / (double)d;

    int64_t q1 = (int64_t)((double)a * 0x1p28 * inv);
    int64_t r1 = (int64_t)((a << 28) - (uint64_t)q1 * d);
    if (r1 < 0)   { q1--; r1 += ds; }
    if (r1 < 0)   { q1--; r1 += ds; }
    if (r1 >= ds) { q1++; r1 -= ds; }

    int64_t q2 = (int64_t)((double)r1 * 0x1p28 * inv);
    int64_t r2 = (int64_t)(((uint64_t)r1 << 28) - (uint64_t)q2 * d);
    if (r2 < 0)   { q2--; r2 += ds; }
    if (r2 < 0)   { q2--; r2 += ds; }
    if (r2 >= ds) { q2++; r2 -= ds; }

    const uint64_t Q = ((uint64_t)q1 << 28) + (uint64_t)q2;  // 57-bit quotient
    const bool remnz = (r2 != 0);

    // Normalize + guard/round/sticky (Q bit 56 = first quotient bit).
    const uint32_t q0 = (uint32_t)(Q >> 56) & 1u;
    uint64_t mant;
    uint32_t rnd;
    bool sticky;
    if (q0) {
        mant   = (Q >> 4) & M52;
        rnd    = (uint32_t)(Q >> 3) & 1u;
        sticky = ((Q & 7ull) != 0ull) || remnz;
    } else {
        mant   = (Q >> 3) & M52;
        rnd    = (uint32_t)(Q >> 2) & 1u;
        sticky = ((Q & 3ull) != 0ull) || remnz;
        exp13  = (exp13 - 1) & 8191;
    }

    // RNE; circuit's 53-bit incrementer carry-out is structurally 0:
    // mantissa overflow wraps to 0 WITHOUT exponent bump (mask only).
    const uint32_t lsb = (uint32_t)mant & 1u;
    const uint32_t rup = (rnd && (sticky || lsb)) ? 1u : 0u;
    mant = (mant + (uint64_t)rup) & M52;

    const uint32_t exp_field = (uint32_t)exp13 & 0x7FFu;
    const bool ovf = ((exp13 >> 11) & 3) != 0;
    const bool unf = (((exp13 >> 12) & 1) != 0) || (exp13 == 0);

    const uint64_t sbit = (uint64_t)s_out << 63;
    uint64_t out;
    if (r_nan)       out = sbit | (0x7FFull << 52) | (1ull << 51);
    else if (r_inf)  out = sbit | (0x7FFull << 52);
    else if (r_zero) out = sbit;
    else if (ovf)    out = sbit | (0x7FFull << 52);
    else if (unf)    out = sbit;
    else             out = sbit | ((uint64_t)exp_field << 52) | mant;

    // ---- Unpack via shuffle: lane k/2 owns row k/2; coalesced STG.32 ----
    const uint32_t hi_o = (uint32_t)(out >> 32);   // cols 0..31  (col c at bit 31-c)
    const uint32_t lo_o = (uint32_t)out;           // cols 32..63 (col 32+c at bit 31-c)
    float* __restrict__ Of = O + elemBase;
    const uint32_t selmask = 1u << (31 - lane);
#pragma unroll
    for (int k = 0; k < 64; k++) {
        const uint32_t w = __shfl_sync(FULL, (k & 1) ? lo_o : hi_o, k >> 1);
        Of[k * 32 + lane] = (w & selmask) ? 1.0f : 0.0f;
    }
}

extern "C" void kernel_launch(void* const* d_in, const int* in_sizes, int n_in,
                              void* d_out, int out_size) {
    const float* A = (const float*)d_in[0];
    const float* B = (const float*)d_in[1];
    float* O = (float*)d_out;
    const int rows = in_sizes[0] / 64;       // 131072
    const int grid = rows / 256;             // 512 blocks, 8 warps x 32 rows
    spike_div_kernel<<<grid, 256>>>(A, B, O);
}